// round 16
// baseline (speedup 1.0000x reference)
#include <cuda_runtime.h>
#include <cuda_fp16.h>
#include <cstdint>

#define Ssz   2304
#define Csz   256
#define Bbat  8
#define BSC   (Bbat*Ssz*Csz)
#define SSl   ((long)Ssz*Ssz)
#define ESIDE ((long)Bbat*Ssz*Ssz)

// ---- scratch (fp16 intermediates) ------------------------------------------
__device__ __half g_xln[2][BSC];
__device__ __half g_q[2][BSC];
__device__ __half g_k[2][BSC];
__device__ __half g_vt[2][BSC];            // V^T: [b][c][t]
__device__ __half g_E[2][(size_t)Bbat*Ssz*Ssz];
__device__ __half g_invD[2][(size_t)Ssz*Ssz];
__device__ __half g_O[2][BSC];
__device__ __half g_Wt[4][Csz*Csz];        // W^T [n][k] fp16

// ---- helpers ---------------------------------------------------------------
__device__ __forceinline__ void mma_f16(float acc[4], const unsigned a[4], const unsigned b[2]) {
    asm volatile(
        "mma.sync.aligned.m16n8k16.row.col.f32.f16.f16.f32 "
        "{%0,%1,%2,%3}, {%4,%5,%6,%7}, {%8,%9}, {%0,%1,%2,%3};\n"
        : "+f"(acc[0]), "+f"(acc[1]), "+f"(acc[2]), "+f"(acc[3])
        : "r"(a[0]), "r"(a[1]), "r"(a[2]), "r"(a[3]), "r"(b[0]), "r"(b[1]));
}
__device__ __forceinline__ void ldsm4(unsigned &r0, unsigned &r1, unsigned &r2, unsigned &r3,
                                      unsigned addr) {
    asm volatile("ldmatrix.sync.aligned.m8n8.x4.shared.b16 {%0,%1,%2,%3}, [%4];"
        : "=r"(r0), "=r"(r1), "=r"(r2), "=r"(r3) : "r"(addr));
}
__device__ __forceinline__ void cpa16(unsigned dst, const void* src) {
    asm volatile("cp.async.cg.shared.global [%0], [%1], 16;" :: "r"(dst), "l"(src));
}
#define CP_COMMIT() asm volatile("cp.async.commit_group;" ::: "memory")
#define CP_WAIT2()  asm volatile("cp.async.wait_group 2;" ::: "memory")

__device__ __forceinline__ unsigned hmul2u(unsigned a, unsigned b) {
    __half2 r = __hmul2(*(__half2*)&a, *(__half2*)&b);
    return *(unsigned*)&r;
}

// XOR-swizzled smem: rows of 32 halfs (64B), 16B segs swizzled by (r + r>>2)&3
__device__ __forceinline__ int swx(int r) { return (r + (r >> 2)) & 3; }
__device__ __forceinline__ unsigned smaddr(unsigned base, int r, int seg) {
    return base + r * 64 + ((seg ^ swx(r)) << 4);
}

// stage: A 8192 | (MODE3: D 8192) | B 8192
#define SMEM_GM (4*16384)   // 65536
#define SMEM_PV (4*24576)   // 98304
#define SMEM_SC (4*16384)

// ---- weight convert: W[k][n] fp32 -> Wt[n][k] fp16 -------------------------
__global__ void wconv_h(const float* __restrict__ wq, const float* __restrict__ wk,
                        const float* __restrict__ wv, const float* __restrict__ wo,
                        __half* __restrict__ wt) {
    int mat = blockIdx.y;
    const float* w = mat == 0 ? wq : mat == 1 ? wk : mat == 2 ? wv : wo;
    int k = blockIdx.x, n = threadIdx.x;
    wt[mat * 65536 + n * 256 + k] = __float2half_rn(w[k * 256 + n]);
}

// ---- LayerNorm over C + transpose [B,C,S]->[B,S,C], fp16 out ---------------
__global__ __launch_bounds__(256, 2) void ln_kernel(
    const float* __restrict__ xl, const float* __restrict__ xr,
    const float* __restrict__ g1, const float* __restrict__ b1,
    const float* __restrict__ g2, const float* __restrict__ b2,
    __half* __restrict__ xlnL, __half* __restrict__ xlnR)
{
    const int side = blockIdx.z;
    const float* x  = side ? xr : xl;
    const float* g  = side ? g2 : g1;
    const float* bb = side ? b2 : b1;
    __half* xo = side ? xlnR : xlnL;

    const int b  = blockIdx.y;
    const int s0 = blockIdx.x * 32;
    const int tid = threadIdx.x;
    const int tx = tid & 31, ty = tid >> 5;

    __shared__ float xs[256][33];
    __shared__ float ps[8][32], ps2[8][32];
    __shared__ float mu[32], rs[32];

    const float* xb = x + (size_t)b * Csz * Ssz;
    #pragma unroll
    for (int cc = 0; cc < 32; cc++) {
        int c = cc * 8 + ty;
        xs[c][tx] = xb[(size_t)c * Ssz + s0 + tx];
    }
    __syncthreads();

    float sum = 0.f, sq = 0.f;
    #pragma unroll
    for (int i = 0; i < 32; i++) {
        float v = xs[ty * 32 + i][tx];
        sum += v; sq += v * v;
    }
    ps[ty][tx] = sum; ps2[ty][tx] = sq;
    __syncthreads();

    if (ty == 0) {
        float s1 = 0.f, s2 = 0.f;
        #pragma unroll
        for (int j = 0; j < 8; j++) { s1 += ps[j][tx]; s2 += ps2[j][tx]; }
        float m = s1 * (1.f / 256.f);
        float v = s2 * (1.f / 256.f) - m * m;
        mu[tx] = m;
        rs[tx] = rsqrtf(v + 1e-5f);
    }
    __syncthreads();

    const float gc = g[tid], bc = bb[tid];
    __half* xob = xo + ((size_t)b * Ssz + s0) * Csz;
    #pragma unroll
    for (int si = 0; si < 32; si++)
        xob[si * Csz + tid] = __float2half_rn((xs[tid][si] - mu[si]) * rs[si] * gc + bc);
}

// ---- fp16 GEMM: C[M,256] = A[M,K] @ Bt[256,K]^T (NT, both k-contig) --------
// CTA tile 128x128 (blockIdx.x encodes m|n), 256 thr, 8 warps (2m x 4n),
// warp tile 64x32, K-chunk 32, 4-stage cp.async, ldmatrix.x4, 2 CTAs/SM.
// MODE 0: C fp16.  MODE 1: Vt via smem transpose.  MODE 2: resid fp32.
// MODE 3: PV — A fragments scaled elementwise by invD[s,t] (fp16) before MMA.
template<int MODE>
__global__ __launch_bounds__(256, 2) void gemm_h(
    const __half* __restrict__ A, int lda, long sA, long sA2,
    const __half* __restrict__ Bt, int ldb, long sB, long sB2,
    void* __restrict__ Cv, long sC, long sC2, int K,
    const float* __restrict__ resid_l, const float* __restrict__ resid_r,
    const __half* __restrict__ Dg)
{
    extern __shared__ char smc[];
    const int tid = threadIdx.x, lane = tid & 31, wid = tid >> 5;
    const int grp = lane >> 2, tg = lane & 3;
    const int wm = (wid & 1) * 64, wn = (wid >> 1) * 32;
    const int m0 = (blockIdx.x >> 1) * 128;
    const int n0 = (blockIdx.x & 1) * 128;
    const int z = blockIdx.y, zs = blockIdx.z;
    A  += (long)z * sA + (long)zs * sA2;
    Bt += (long)z * sB + (long)zs * sB2;
    const __half* Dv = (MODE == 3) ? (Dg + (long)zs * SSl) : nullptr;

    constexpr int STG  = (MODE == 3) ? 24576 : 16384;
    constexpr int BOFF = (MODE == 3) ? 16384 : 8192;

    const unsigned sbu = (unsigned)__cvta_generic_to_shared(smc);
    const int la  = lane & 7;
    const int lb8 = ((lane >> 3) & 1) * 8;
    const int lc16 = lane >> 4;
    const int arow0 = wm + la + lb8;
    const int brow0 = wn + la + (lane >> 4) * 8;
    const int bseg0 = (lane >> 3) & 1;

    auto ldgsts = [&](int kc, int stg) {
        unsigned Asu = sbu + stg * STG;
        unsigned Bsu = Asu + BOFF;
        #pragma unroll
        for (int p = 0; p < 2; p++) {
            int idx = p * 256 + tid, row = idx >> 2, sg = idx & 3;
            cpa16(smaddr(Asu, row, sg), &A[(long)(m0 + row) * lda + kc * 32 + sg * 8]);
            cpa16(smaddr(Bsu, row, sg), &Bt[(long)(n0 + row) * ldb + kc * 32 + sg * 8]);
            if (MODE == 3)
                cpa16(smaddr(Asu + 8192, row, sg),
                      &Dv[(long)(m0 + row) * Ssz + kc * 32 + sg * 8]);
        }
    };

    float acc[4][4][4];
    #pragma unroll
    for (int i = 0; i < 4; i++)
        #pragma unroll
        for (int j = 0; j < 4; j++)
            #pragma unroll
            for (int r = 0; r < 4; r++) acc[i][j][r] = 0.f;

    const int nch = K >> 5;
    #pragma unroll
    for (int p = 0; p < 3; p++) { ldgsts(p, p); CP_COMMIT(); }

    for (int ic = 0; ic < nch; ic++) {
        CP_WAIT2();
        __syncthreads();
        const unsigned Asu = sbu + (ic & 3) * STG;
        const unsigned Bsu = Asu + BOFF;
        #pragma unroll
        for (int ks = 0; ks < 2; ks++) {
            const int s0seg = ks * 2;
            unsigned af[4][4], bf[4][2];
            #pragma unroll
            for (int mi = 0; mi < 4; mi++) {
                ldsm4(af[mi][0], af[mi][1], af[mi][2], af[mi][3],
                      smaddr(Asu, arow0 + mi * 16, s0seg + lc16));
                if (MODE == 3) {
                    unsigned dv0, dv1, dv2, dv3;
                    ldsm4(dv0, dv1, dv2, dv3,
                          smaddr(Asu + 8192, arow0 + mi * 16, s0seg + lc16));
                    af[mi][0] = hmul2u(af[mi][0], dv0);
                    af[mi][1] = hmul2u(af[mi][1], dv1);
                    af[mi][2] = hmul2u(af[mi][2], dv2);
                    af[mi][3] = hmul2u(af[mi][3], dv3);
                }
            }
            #pragma unroll
            for (int np = 0; np < 2; np++)
                ldsm4(bf[2 * np][0], bf[2 * np][1], bf[2 * np + 1][0], bf[2 * np + 1][1],
                      smaddr(Bsu, brow0 + np * 16, s0seg + bseg0));
            #pragma unroll
            for (int mi = 0; mi < 4; mi++)
                #pragma unroll
                for (int ni = 0; ni < 4; ni++)
                    mma_f16(acc[mi][ni], af[mi], bf[ni]);
        }
        if (ic + 3 < nch) ldgsts(ic + 3, (ic + 3) & 3);
        CP_COMMIT();
    }

    if (MODE == 0 || MODE == 3) {
        __half* C = (__half*)Cv + (long)z * sC + (long)zs * sC2;
        #pragma unroll
        for (int mi = 0; mi < 4; mi++) {
            #pragma unroll
            for (int ni = 0; ni < 4; ni++) {
                int r0 = m0 + wm + mi * 16 + grp;
                int c0 = n0 + wn + ni * 8 + tg * 2;
                *(__half2*)&C[(long)r0 * 256 + c0] =
                    __floats2half2_rn(acc[mi][ni][0], acc[mi][ni][1]);
                *(__half2*)&C[(long)(r0 + 8) * 256 + c0] =
                    __floats2half2_rn(acc[mi][ni][2], acc[mi][ni][3]);
            }
        }
    } else if (MODE == 1) {
        __syncthreads();
        __half* tb = (__half*)smc;              // [128][136]
        #pragma unroll
        for (int mi = 0; mi < 4; mi++) {
            #pragma unroll
            for (int ni = 0; ni < 4; ni++) {
                int r  = wm + mi * 16 + grp;
                int c0 = wn + ni * 8 + tg * 2;
                tb[c0 * 136 + r]           = __float2half_rn(acc[mi][ni][0]);
                tb[(c0 + 1) * 136 + r]     = __float2half_rn(acc[mi][ni][1]);
                tb[c0 * 136 + r + 8]       = __float2half_rn(acc[mi][ni][2]);
                tb[(c0 + 1) * 136 + r + 8] = __float2half_rn(acc[mi][ni][3]);
            }
        }
        __syncthreads();
        const int bb = m0 / Ssz, s0m = m0 - bb * Ssz;
        __half* C = (__half*)Cv + (long)z * sC + (long)zs * sC2;
        #pragma unroll
        for (int p = 0; p < 8; p++) {
            int idx = p * 256 + tid;
            int c = idx >> 4, ms = idx & 15;
            uint4 v = *(uint4*)&tb[c * 136 + ms * 8];
            *(uint4*)&C[((long)(bb * 256 + n0 + c)) * Ssz + s0m + ms * 8] = v;
        }
    } else {
        const float* resid = zs ? resid_r : resid_l;
        float* C = (float*)Cv + (long)zs * sC2;
        #pragma unroll
        for (int mi = 0; mi < 4; mi++) {
            #pragma unroll
            for (int ni = 0; ni < 4; ni++) {
                int r0 = m0 + wm + mi * 16 + grp;
                int c0 = n0 + wn + ni * 8 + tg * 2;
                int bb = r0 / Ssz;
                int ss = r0 - bb * Ssz;
                long a0 = ((long)(bb * 256 + c0)) * Ssz + ss;
                C[a0          ] = resid[a0          ] + acc[mi][ni][0];
                C[a0 + Ssz    ] = resid[a0 + Ssz    ] + acc[mi][ni][1];
                C[a0 + 8      ] = resid[a0 + 8      ] + acc[mi][ni][2];
                C[a0 + Ssz + 8] = resid[a0 + Ssz + 8] + acc[mi][ni][3];
            }
        }
    }
}

// ---- scores: E[side,b,s,t] = exp(Q·K^T / 16) fp16, 8 batches per CTA -------
// grid (18 t-tiles, 18 s-tiles, 2 sides); CTA 128s x 128t, 2 CTAs/SM.
__global__ __launch_bounds__(256, 2) void sc_h(
    const __half* __restrict__ qb, const __half* __restrict__ kb,
    __half* __restrict__ Eg)
{
    extern __shared__ char smc[];
    const int tid = threadIdx.x, lane = tid & 31, wid = tid >> 5;
    const int grp = lane >> 2, tg = lane & 3;
    const int wm = (wid & 1) * 64, wn = (wid >> 1) * 32;
    const int s0 = blockIdx.y * 128, t0 = blockIdx.x * 128;
    const int side = blockIdx.z;

    const __half* Q  = qb + (long)side * BSC;
    const __half* Ko = kb + (long)(side ^ 1) * BSC;
    __half* E = Eg + (long)side * ESIDE;

    const unsigned sbu = (unsigned)__cvta_generic_to_shared(smc);
    const int la  = lane & 7;
    const int lb8 = ((lane >> 3) & 1) * 8;
    const int lc16 = lane >> 4;
    const int arow0 = wm + la + lb8;
    const int brow0 = wn + la + (lane >> 4) * 8;
    const int bseg0 = (lane >> 3) & 1;

    auto ldgsts = [&](int it, int stg) {
        int b = it >> 3, kc = it & 7;
        const __half* qa = Q  + ((long)b * Ssz + s0) * 256;
        const __half* ka = Ko + ((long)b * Ssz + t0) * 256;
        unsigned Asu = sbu + stg * 16384;
        unsigned Bsu = Asu + 8192;
        #pragma unroll
        for (int p = 0; p < 2; p++) {
            int idx = p * 256 + tid, row = idx >> 2, sg = idx & 3;
            cpa16(smaddr(Asu, row, sg), &qa[(long)row * 256 + kc * 32 + sg * 8]);
            cpa16(smaddr(Bsu, row, sg), &ka[(long)row * 256 + kc * 32 + sg * 8]);
        }
    };

    float acc[4][4][4];
    #pragma unroll
    for (int p = 0; p < 3; p++) { ldgsts(p, p); CP_COMMIT(); }

    for (int it = 0; it < 64; it++) {
        CP_WAIT2();
        __syncthreads();

        if ((it & 7) == 0) {
            #pragma unroll
            for (int i = 0; i < 4; i++)
                #pragma unroll
                for (int j = 0; j < 4; j++)
                    #pragma unroll
                    for (int r = 0; r < 4; r++) acc[i][j][r] = 0.f;
        }

        const unsigned Asu = sbu + (it & 3) * 16384;
        const unsigned Bsu = Asu + 8192;
        #pragma unroll
        for (int ks = 0; ks < 2; ks++) {
            const int s0seg = ks * 2;
            unsigned af[4][4], bf[4][2];
            #pragma unroll
            for (int mi = 0; mi < 4; mi++)
                ldsm4(af[mi][0], af[mi][1], af[mi][2], af[mi][3],
                      smaddr(Asu, arow0 + mi * 16, s0seg + lc16));
            #pragma unroll
            for (int np = 0; np < 2; np++)
                ldsm4(bf[2 * np][0], bf[2 * np][1], bf[2 * np + 1][0], bf[2 * np + 1][1],
                      smaddr(Bsu, brow0 + np * 16, s0seg + bseg0));
            #pragma unroll
            for (int mi = 0; mi < 4; mi++)
                #pragma unroll
                for (int ni = 0; ni < 4; ni++)
                    mma_f16(acc[mi][ni], af[mi], bf[ni]);
        }

        if ((it & 7) == 7) {
            const int b = it >> 3;
            __half* Eb = E + (long)b * SSl;
            #pragma unroll
            for (int mi = 0; mi < 4; mi++) {
                #pragma unroll
                for (int ni = 0; ni < 4; ni++) {
                    int r0 = s0 + wm + mi * 16 + grp;
                    int c0 = t0 + wn + ni * 8 + tg * 2;
                    *(__half2*)&Eb[(long)r0 * Ssz + c0] =
                        __floats2half2_rn(__expf(acc[mi][ni][0] * 0.0625f),
                                          __expf(acc[mi][ni][1] * 0.0625f));
                    *(__half2*)&Eb[(long)(r0 + 8) * Ssz + c0] =
                        __floats2half2_rn(__expf(acc[mi][ni][2] * 0.0625f),
                                          __expf(acc[mi][ni][3] * 0.0625f));
                }
            }
        }
        if (it + 3 < 64) ldgsts(it + 3, (it + 3) & 3);
        CP_COMMIT();
    }
}

// ---- denom: invD[s,t] = 1/sum_b E[b,s,t] (fp16 out, per side) --------------
__global__ __launch_bounds__(256, 4) void denom_h(const __half* __restrict__ Eg,
                                                  __half* __restrict__ Dg)
{
    const __half* E = Eg + (long)blockIdx.y * ESIDE;
    __half* D = Dg + (long)blockIdx.y * SSl;
    long i = ((long)blockIdx.x * 256 + threadIdx.x) * 8;
    float s[8] = {0.f, 0.f, 0.f, 0.f, 0.f, 0.f, 0.f, 0.f};
    #pragma unroll
    for (int b = 0; b < Bbat; b++) {
        uint4 ev = *(const uint4*)&E[b * SSl + i];
        const __half2* h2 = (const __half2*)&ev;
        #pragma unroll
        for (int j = 0; j < 4; j++) {
            float2 f = __half22float2(h2[j]);
            s[2 * j] += f.x; s[2 * j + 1] += f.y;
        }
    }
    uint4 ov;
    __half2* o2 = (__half2*)&ov;
    #pragma unroll
    for (int j = 0; j < 4; j++)
        o2[j] = __floats2half2_rn(1.f / s[2 * j], 1.f / s[2 * j + 1]);
    *(uint4*)&D[i] = ov;
}

// ---- launch ----------------------------------------------------------------
extern "C" void kernel_launch(void* const* d_in, const int* in_sizes, int n_in,
                              void* d_out, int out_size) {
    const float* x_l = (const float*)d_in[0];
    const float* x_r = (const float*)d_in[1];
    const float* Wq  = (const float*)d_in[2];
    const float* Wk  = (const float*)d_in[3];
    const float* Wv  = (const float*)d_in[4];
    const float* Wo  = (const float*)d_in[5];
    const float* g1  = (const float*)d_in[6];
    const float* b1  = (const float*)d_in[7];
    const float* g2  = (const float*)d_in[8];
    const float* b2  = (const float*)d_in[9];
    float* out = (float*)d_out;

    __half *xln, *q, *k, *vt, *E, *invD, *O, *Wt;
    cudaGetSymbolAddress((void**)&xln,  g_xln);
    cudaGetSymbolAddress((void**)&q,    g_q);
    cudaGetSymbolAddress((void**)&k,    g_k);
    cudaGetSymbolAddress((void**)&vt,   g_vt);
    cudaGetSymbolAddress((void**)&E,    g_E);
    cudaGetSymbolAddress((void**)&invD, g_invD);
    cudaGetSymbolAddress((void**)&O,    g_O);
    cudaGetSymbolAddress((void**)&Wt,   g_Wt);

    cudaFuncSetAttribute(gemm_h<0>, cudaFuncAttributeMaxDynamicSharedMemorySize, SMEM_GM);
    cudaFuncSetAttribute(gemm_h<1>, cudaFuncAttributeMaxDynamicSharedMemorySize, SMEM_GM);
    cudaFuncSetAttribute(gemm_h<2>, cudaFuncAttributeMaxDynamicSharedMemorySize, SMEM_GM);
    cudaFuncSetAttribute(gemm_h<3>, cudaFuncAttributeMaxDynamicSharedMemorySize, SMEM_PV);
    cudaFuncSetAttribute(sc_h,      cudaFuncAttributeMaxDynamicSharedMemorySize, SMEM_SC);

    wconv_h<<<dim3(256, 4), 256>>>(Wq, Wk, Wv, Wo, Wt);
    ln_kernel<<<dim3(Ssz / 32, Bbat, 2), 256>>>(x_l, x_r, g1, b1, g2, b2,
                                                xln, xln + BSC);

    // Q, K, V projections — both sides per launch (576 CTAs each)
    gemm_h<0><<<dim3(288, 1, 2), 256, SMEM_GM>>>(xln, 256, 0, BSC,
                                                 Wt + 0 * 65536, 256, 0, 0,
                                                 q, 0, BSC, 256, nullptr, nullptr, nullptr);
    gemm_h<0><<<dim3(288, 1, 2), 256, SMEM_GM>>>(xln, 256, 0, BSC,
                                                 Wt + 1 * 65536, 256, 0, 0,
                                                 k, 0, BSC, 256, nullptr, nullptr, nullptr);
    gemm_h<1><<<dim3(288, 1, 2), 256, SMEM_GM>>>(xln, 256, 0, BSC,
                                                 Wt + 2 * 65536, 256, 0, 0,
                                                 vt, 0, BSC, 256, nullptr, nullptr, nullptr);

    // scores for both sides (648 CTAs), raw exp
    sc_h<<<dim3(18, 18, 2), 256, SMEM_SC>>>(q, k, E);
    // batch-denominator -> fp16 invD (reads E once, writes 21 MB)
    denom_h<<<dim3((int)(SSl / 2048), 2), 256>>>(E, invD);
    // PV with invD folded into A fragments (576 CTAs)
    gemm_h<3><<<dim3(36, Bbat, 2), 256, SMEM_PV>>>(E, Ssz, SSl, ESIDE,
                                                   vt, Ssz, (long)Csz * Ssz, (long)BSC,
                                                   O, (long)Ssz * Csz, (long)BSC,
                                                   Ssz, nullptr, nullptr, invD);
    // output projection + residual + transpose back, both sides (576 CTAs)
    gemm_h<2><<<dim3(288, 1, 2), 256, SMEM_GM>>>(O, 256, 0, BSC,
                                                 Wt + 3 * 65536, 256, 0, 0,
                                                 out, 0, BSC, 256, x_l, x_r, nullptr);
}

// round 17
// speedup vs baseline: 1.0313x; 1.0313x over previous
#include <cuda_runtime.h>
#include <cuda_fp16.h>
#include <cstdint>

#define Ssz   2304
#define Csz   256
#define Bbat  8
#define BSC   (Bbat*Ssz*Csz)
#define SSl   ((long)Ssz*Ssz)
#define ESIDE ((long)Bbat*Ssz*Ssz)

// ---- scratch (fp16 intermediates) ------------------------------------------
__device__ __half g_xln[2][BSC];
__device__ __half g_q[2][BSC];
__device__ __half g_k[2][BSC];
__device__ __half g_vt[2][BSC];            // V^T: [b][c][t]
__device__ __half g_E[2][(size_t)Bbat*Ssz*Ssz];
__device__ __half g_O[2][BSC];
__device__ __half g_Wt[4][Csz*Csz];        // W^T [n][k] fp16

// ---- helpers ---------------------------------------------------------------
__device__ __forceinline__ void mma_f16(float acc[4], const unsigned a[4], const unsigned b[2]) {
    asm volatile(
        "mma.sync.aligned.m16n8k16.row.col.f32.f16.f16.f32 "
        "{%0,%1,%2,%3}, {%4,%5,%6,%7}, {%8,%9}, {%0,%1,%2,%3};\n"
        : "+f"(acc[0]), "+f"(acc[1]), "+f"(acc[2]), "+f"(acc[3])
        : "r"(a[0]), "r"(a[1]), "r"(a[2]), "r"(a[3]), "r"(b[0]), "r"(b[1]));
}
__device__ __forceinline__ void ldsm4(unsigned &r0, unsigned &r1, unsigned &r2, unsigned &r3,
                                      unsigned addr) {
    asm volatile("ldmatrix.sync.aligned.m8n8.x4.shared.b16 {%0,%1,%2,%3}, [%4];"
        : "=r"(r0), "=r"(r1), "=r"(r2), "=r"(r3) : "r"(addr));
}
__device__ __forceinline__ void cpa16(unsigned dst, const void* src) {
    asm volatile("cp.async.cg.shared.global [%0], [%1], 16;" :: "r"(dst), "l"(src));
}
#define CP_COMMIT() asm volatile("cp.async.commit_group;" ::: "memory")
#define CP_WAIT1()  asm volatile("cp.async.wait_group 1;" ::: "memory")

// XOR-swizzled smem: rows of 32 halfs (64B), 16B segs swizzled by (r + r>>2)&3
__device__ __forceinline__ int swx(int r) { return (r + (r >> 2)) & 3; }
__device__ __forceinline__ unsigned smaddr(unsigned base, int r, int seg) {
    return base + r * 64 + ((seg ^ swx(r)) << 4);
}

// K64 stage = 32 KB: [A(k0:31) 8K][B(k0:31) 8K][A(k32:63) 8K][B(k32:63) 8K]
// 3 stages = 96 KB per CTA -> 2 CTAs/SM.
#define STG_B   32768
#define SMEM_ALL (3*STG_B)   // 98304

// ---- weight convert: W[k][n] fp32 -> Wt[n][k] fp16 -------------------------
__global__ void wconv_h(const float* __restrict__ wq, const float* __restrict__ wk,
                        const float* __restrict__ wv, const float* __restrict__ wo,
                        __half* __restrict__ wt) {
    int mat = blockIdx.y;
    const float* w = mat == 0 ? wq : mat == 1 ? wk : mat == 2 ? wv : wo;
    int k = blockIdx.x, n = threadIdx.x;
    wt[mat * 65536 + n * 256 + k] = __float2half_rn(w[k * 256 + n]);
}

// ---- LayerNorm over C + transpose [B,C,S]->[B,S,C], fp16 out ---------------
__global__ __launch_bounds__(256, 2) void ln_kernel(
    const float* __restrict__ xl, const float* __restrict__ xr,
    const float* __restrict__ g1, const float* __restrict__ b1,
    const float* __restrict__ g2, const float* __restrict__ b2,
    __half* __restrict__ xlnL, __half* __restrict__ xlnR)
{
    const int side = blockIdx.z;
    const float* x  = side ? xr : xl;
    const float* g  = side ? g2 : g1;
    const float* bb = side ? b2 : b1;
    __half* xo = side ? xlnR : xlnL;

    const int b  = blockIdx.y;
    const int s0 = blockIdx.x * 32;
    const int tid = threadIdx.x;
    const int tx = tid & 31, ty = tid >> 5;

    __shared__ float xs[256][33];
    __shared__ float ps[8][32], ps2[8][32];
    __shared__ float mu[32], rs[32];

    const float* xb = x + (size_t)b * Csz * Ssz;
    #pragma unroll
    for (int cc = 0; cc < 32; cc++) {
        int c = cc * 8 + ty;
        xs[c][tx] = xb[(size_t)c * Ssz + s0 + tx];
    }
    __syncthreads();

    float sum = 0.f, sq = 0.f;
    #pragma unroll
    for (int i = 0; i < 32; i++) {
        float v = xs[ty * 32 + i][tx];
        sum += v; sq += v * v;
    }
    ps[ty][tx] = sum; ps2[ty][tx] = sq;
    __syncthreads();

    if (ty == 0) {
        float s1 = 0.f, s2 = 0.f;
        #pragma unroll
        for (int j = 0; j < 8; j++) { s1 += ps[j][tx]; s2 += ps2[j][tx]; }
        float m = s1 * (1.f / 256.f);
        float v = s2 * (1.f / 256.f) - m * m;
        mu[tx] = m;
        rs[tx] = rsqrtf(v + 1e-5f);
    }
    __syncthreads();

    const float gc = g[tid], bc = bb[tid];
    __half* xob = xo + ((size_t)b * Ssz + s0) * Csz;
    #pragma unroll
    for (int si = 0; si < 32; si++)
        xob[si * Csz + tid] = __float2half_rn((xs[tid][si] - mu[si]) * rs[si] * gc + bc);
}

// ---- fp16 GEMM: C[M,256] = A[M,K] @ Bt[256,K]^T (NT, both k-contig) --------
// CTA tile 128x128 (blockIdx.x encodes m|n), 256 thr, 8 warps (2m x 4n),
// warp tile 64x32, K-chunk 64, 3-stage cp.async, ldmatrix.x4, 2 CTAs/SM.
// MODE 0: C fp16.  MODE 1: Vt via smem transpose.  MODE 2: resid fp32.
template<int MODE>
__global__ __launch_bounds__(256, 2) void gemm_h(
    const __half* __restrict__ A, int lda, long sA, long sA2,
    const __half* __restrict__ Bt, int ldb, long sB, long sB2,
    void* __restrict__ Cv, long sC, long sC2, int K,
    const float* __restrict__ resid_l, const float* __restrict__ resid_r)
{
    extern __shared__ char smc[];
    const int tid = threadIdx.x, lane = tid & 31, wid = tid >> 5;
    const int grp = lane >> 2, tg = lane & 3;
    const int wm = (wid & 1) * 64, wn = (wid >> 1) * 32;
    const int m0 = (blockIdx.x >> 1) * 128;
    const int n0 = (blockIdx.x & 1) * 128;
    const int z = blockIdx.y, zs = blockIdx.z;
    A  += (long)z * sA + (long)zs * sA2;
    Bt += (long)z * sB + (long)zs * sB2;

    const unsigned sbu = (unsigned)__cvta_generic_to_shared(smc);
    const int la  = lane & 7;
    const int lb8 = ((lane >> 3) & 1) * 8;
    const int lc16 = lane >> 4;
    const int arow0 = wm + la + lb8;
    const int brow0 = wn + la + (lane >> 4) * 8;
    const int bseg0 = (lane >> 3) & 1;

    auto ldgsts = [&](int kc, int stg) {       // kc: 64-elem chunk index
        unsigned base = sbu + stg * STG_B;
        #pragma unroll
        for (int sub = 0; sub < 2; sub++) {
            unsigned Asu = base + sub * 16384;
            unsigned Bsu = Asu + 8192;
            int k0 = kc * 64 + sub * 32;
            #pragma unroll
            for (int p = 0; p < 2; p++) {
                int idx = p * 256 + tid, row = idx >> 2, sg = idx & 3;
                cpa16(smaddr(Asu, row, sg), &A[(long)(m0 + row) * lda + k0 + sg * 8]);
                cpa16(smaddr(Bsu, row, sg), &Bt[(long)(n0 + row) * ldb + k0 + sg * 8]);
            }
        }
    };

    float acc[4][4][4];
    #pragma unroll
    for (int i = 0; i < 4; i++)
        #pragma unroll
        for (int j = 0; j < 4; j++)
            #pragma unroll
            for (int r = 0; r < 4; r++) acc[i][j][r] = 0.f;

    const int nch = K >> 6;
    #pragma unroll
    for (int p = 0; p < 2; p++) { ldgsts(p, p); CP_COMMIT(); }

    int st = 0;
    for (int ic = 0; ic < nch; ic++) {
        CP_WAIT1();
        __syncthreads();
        const unsigned base = sbu + st * STG_B;
        st = (st == 2) ? 0 : st + 1;
        #pragma unroll
        for (int sub = 0; sub < 2; sub++) {
            const unsigned Asu = base + sub * 16384;
            const unsigned Bsu = Asu + 8192;
            #pragma unroll
            for (int ks = 0; ks < 2; ks++) {
                const int s0seg = ks * 2;
                unsigned af[4][4], bf[4][2];
                #pragma unroll
                for (int mi = 0; mi < 4; mi++)
                    ldsm4(af[mi][0], af[mi][1], af[mi][2], af[mi][3],
                          smaddr(Asu, arow0 + mi * 16, s0seg + lc16));
                #pragma unroll
                for (int np = 0; np < 2; np++)
                    ldsm4(bf[2 * np][0], bf[2 * np][1], bf[2 * np + 1][0], bf[2 * np + 1][1],
                          smaddr(Bsu, brow0 + np * 16, s0seg + bseg0));
                #pragma unroll
                for (int mi = 0; mi < 4; mi++)
                    #pragma unroll
                    for (int ni = 0; ni < 4; ni++)
                        mma_f16(acc[mi][ni], af[mi], bf[ni]);
            }
        }
        if (ic + 2 < nch) ldgsts(ic + 2, (ic + 2) % 3);
        CP_COMMIT();
    }

    if (MODE == 0) {
        __half* C = (__half*)Cv + (long)z * sC + (long)zs * sC2;
        #pragma unroll
        for (int mi = 0; mi < 4; mi++) {
            #pragma unroll
            for (int ni = 0; ni < 4; ni++) {
                int r0 = m0 + wm + mi * 16 + grp;
                int c0 = n0 + wn + ni * 8 + tg * 2;
                *(__half2*)&C[(long)r0 * 256 + c0] =
                    __floats2half2_rn(acc[mi][ni][0], acc[mi][ni][1]);
                *(__half2*)&C[(long)(r0 + 8) * 256 + c0] =
                    __floats2half2_rn(acc[mi][ni][2], acc[mi][ni][3]);
            }
        }
    } else if (MODE == 1) {
        __syncthreads();
        __half* tb = (__half*)smc;              // [128][136]
        #pragma unroll
        for (int mi = 0; mi < 4; mi++) {
            #pragma unroll
            for (int ni = 0; ni < 4; ni++) {
                int r  = wm + mi * 16 + grp;
                int c0 = wn + ni * 8 + tg * 2;
                tb[c0 * 136 + r]           = __float2half_rn(acc[mi][ni][0]);
                tb[(c0 + 1) * 136 + r]     = __float2half_rn(acc[mi][ni][1]);
                tb[c0 * 136 + r + 8]       = __float2half_rn(acc[mi][ni][2]);
                tb[(c0 + 1) * 136 + r + 8] = __float2half_rn(acc[mi][ni][3]);
            }
        }
        __syncthreads();
        const int bb = m0 / Ssz, s0m = m0 - bb * Ssz;
        __half* C = (__half*)Cv + (long)z * sC + (long)zs * sC2;
        #pragma unroll
        for (int p = 0; p < 8; p++) {
            int idx = p * 256 + tid;
            int c = idx >> 4, ms = idx & 15;
            uint4 v = *(uint4*)&tb[c * 136 + ms * 8];
            *(uint4*)&C[((long)(bb * 256 + n0 + c)) * Ssz + s0m + ms * 8] = v;
        }
    } else {
        const float* resid = zs ? resid_r : resid_l;
        float* C = (float*)Cv + (long)zs * sC2;
        #pragma unroll
        for (int mi = 0; mi < 4; mi++) {
            #pragma unroll
            for (int ni = 0; ni < 4; ni++) {
                int r0 = m0 + wm + mi * 16 + grp;
                int c0 = n0 + wn + ni * 8 + tg * 2;
                int bb = r0 / Ssz;
                int ss = r0 - bb * Ssz;
                long a0 = ((long)(bb * 256 + c0)) * Ssz + ss;
                C[a0          ] = resid[a0          ] + acc[mi][ni][0];
                C[a0 + Ssz    ] = resid[a0 + Ssz    ] + acc[mi][ni][1];
                C[a0 + 8      ] = resid[a0 + 8      ] + acc[mi][ni][2];
                C[a0 + Ssz + 8] = resid[a0 + Ssz + 8] + acc[mi][ni][3];
            }
        }
    }
}

// ---- scores: E[side,b,s,t] = exp(Q·K^T / 16) fp16, 8 batches per CTA -------
// grid (18 t-tiles, 18 s-tiles, 2 sides); CTA 128s x 128t, K-chunk 64.
__global__ __launch_bounds__(256, 2) void sc_h(
    const __half* __restrict__ qb, const __half* __restrict__ kb,
    __half* __restrict__ Eg)
{
    extern __shared__ char smc[];
    const int tid = threadIdx.x, lane = tid & 31, wid = tid >> 5;
    const int grp = lane >> 2, tg = lane & 3;
    const int wm = (wid & 1) * 64, wn = (wid >> 1) * 32;
    const int s0 = blockIdx.y * 128, t0 = blockIdx.x * 128;
    const int side = blockIdx.z;

    const __half* Q  = qb + (long)side * BSC;
    const __half* Ko = kb + (long)(side ^ 1) * BSC;
    __half* E = Eg + (long)side * ESIDE;

    const unsigned sbu = (unsigned)__cvta_generic_to_shared(smc);
    const int la  = lane & 7;
    const int lb8 = ((lane >> 3) & 1) * 8;
    const int lc16 = lane >> 4;
    const int arow0 = wm + la + lb8;
    const int brow0 = wn + la + (lane >> 4) * 8;
    const int bseg0 = (lane >> 3) & 1;

    auto ldgsts = [&](int it, int stg) {   // it: 0..31, b=it>>2, kc64=it&3
        int b = it >> 2, kc = it & 3;
        const __half* qa = Q  + ((long)b * Ssz + s0) * 256;
        const __half* ka = Ko + ((long)b * Ssz + t0) * 256;
        unsigned base = sbu + stg * STG_B;
        #pragma unroll
        for (int sub = 0; sub < 2; sub++) {
            unsigned Asu = base + sub * 16384;
            unsigned Bsu = Asu + 8192;
            int k0 = kc * 64 + sub * 32;
            #pragma unroll
            for (int p = 0; p < 2; p++) {
                int idx = p * 256 + tid, row = idx >> 2, sg = idx & 3;
                cpa16(smaddr(Asu, row, sg), &qa[(long)row * 256 + k0 + sg * 8]);
                cpa16(smaddr(Bsu, row, sg), &ka[(long)row * 256 + k0 + sg * 8]);
            }
        }
    };

    float acc[4][4][4];
    #pragma unroll
    for (int p = 0; p < 2; p++) { ldgsts(p, p); CP_COMMIT(); }

    int st = 0;
    for (int it = 0; it < 32; it++) {
        CP_WAIT1();
        __syncthreads();

        if ((it & 3) == 0) {
            #pragma unroll
            for (int i = 0; i < 4; i++)
                #pragma unroll
                for (int j = 0; j < 4; j++)
                    #pragma unroll
                    for (int r = 0; r < 4; r++) acc[i][j][r] = 0.f;
        }

        const unsigned base = sbu + st * STG_B;
        st = (st == 2) ? 0 : st + 1;
        #pragma unroll
        for (int sub = 0; sub < 2; sub++) {
            const unsigned Asu = base + sub * 16384;
            const unsigned Bsu = Asu + 8192;
            #pragma unroll
            for (int ks = 0; ks < 2; ks++) {
                const int s0seg = ks * 2;
                unsigned af[4][4], bf[4][2];
                #pragma unroll
                for (int mi = 0; mi < 4; mi++)
                    ldsm4(af[mi][0], af[mi][1], af[mi][2], af[mi][3],
                          smaddr(Asu, arow0 + mi * 16, s0seg + lc16));
                #pragma unroll
                for (int np = 0; np < 2; np++)
                    ldsm4(bf[2 * np][0], bf[2 * np][1], bf[2 * np + 1][0], bf[2 * np + 1][1],
                          smaddr(Bsu, brow0 + np * 16, s0seg + bseg0));
                #pragma unroll
                for (int mi = 0; mi < 4; mi++)
                    #pragma unroll
                    for (int ni = 0; ni < 4; ni++)
                        mma_f16(acc[mi][ni], af[mi], bf[ni]);
            }
        }

        if ((it & 3) == 3) {
            const int b = it >> 2;
            __half* Eb = E + (long)b * SSl;
            #pragma unroll
            for (int mi = 0; mi < 4; mi++) {
                #pragma unroll
                for (int ni = 0; ni < 4; ni++) {
                    int r0 = s0 + wm + mi * 16 + grp;
                    int c0 = t0 + wn + ni * 8 + tg * 2;
                    *(__half2*)&Eb[(long)r0 * Ssz + c0] =
                        __floats2half2_rn(__expf(acc[mi][ni][0] * 0.0625f),
                                          __expf(acc[mi][ni][1] * 0.0625f));
                    *(__half2*)&Eb[(long)(r0 + 8) * Ssz + c0] =
                        __floats2half2_rn(__expf(acc[mi][ni][2] * 0.0625f),
                                          __expf(acc[mi][ni][3] * 0.0625f));
                }
            }
        }
        if (it + 2 < 32) ldgsts(it + 2, (it + 2) % 3);
        CP_COMMIT();
    }
}

// ---- normalize: E[b,s,t] /= sum_b E[b,s,t] (fp16, in place, per side) ------
__global__ __launch_bounds__(256, 4) void normalize_h(__half* __restrict__ Eg)
{
    __half* E = Eg + (long)blockIdx.y * ESIDE;
    long i = ((long)blockIdx.x * 256 + threadIdx.x) * 8;
    uint4 ev[Bbat];
    float s[8] = {0.f, 0.f, 0.f, 0.f, 0.f, 0.f, 0.f, 0.f};
    #pragma unroll
    for (int b = 0; b < Bbat; b++) {
        ev[b] = *(const uint4*)&E[b * SSl + i];
        const __half2* h2 = (const __half2*)&ev[b];
        #pragma unroll
        for (int j = 0; j < 4; j++) {
            float2 f = __half22float2(h2[j]);
            s[2 * j] += f.x; s[2 * j + 1] += f.y;
        }
    }
    float inv[8];
    #pragma unroll
    for (int j = 0; j < 8; j++) inv[j] = 1.f / s[j];
    #pragma unroll
    for (int b = 0; b < Bbat; b++) {
        __half2* h2 = (__half2*)&ev[b];
        #pragma unroll
        for (int j = 0; j < 4; j++) {
            float2 f = __half22float2(h2[j]);
            h2[j] = __floats2half2_rn(f.x * inv[2 * j], f.y * inv[2 * j + 1]);
        }
        *(uint4*)&E[b * SSl + i] = ev[b];
    }
}

// ---- launch ----------------------------------------------------------------
extern "C" void kernel_launch(void* const* d_in, const int* in_sizes, int n_in,
                              void* d_out, int out_size) {
    const float* x_l = (const float*)d_in[0];
    const float* x_r = (const float*)d_in[1];
    const float* Wq  = (const float*)d_in[2];
    const float* Wk  = (const float*)d_in[3];
    const float* Wv  = (const float*)d_in[4];
    const float* Wo  = (const float*)d_in[5];
    const float* g1  = (const float*)d_in[6];
    const float* b1  = (const float*)d_in[7];
    const float* g2  = (const float*)d_in[8];
    const float* b2  = (const float*)d_in[9];
    float* out = (float*)d_out;

    __half *xln, *q, *k, *vt, *E, *O, *Wt;
    cudaGetSymbolAddress((void**)&xln, g_xln);
    cudaGetSymbolAddress((void**)&q,   g_q);
    cudaGetSymbolAddress((void**)&k,   g_k);
    cudaGetSymbolAddress((void**)&vt,  g_vt);
    cudaGetSymbolAddress((void**)&E,   g_E);
    cudaGetSymbolAddress((void**)&O,   g_O);
    cudaGetSymbolAddress((void**)&Wt,  g_Wt);

    cudaFuncSetAttribute(gemm_h<0>, cudaFuncAttributeMaxDynamicSharedMemorySize, SMEM_ALL);
    cudaFuncSetAttribute(gemm_h<1>, cudaFuncAttributeMaxDynamicSharedMemorySize, SMEM_ALL);
    cudaFuncSetAttribute(gemm_h<2>, cudaFuncAttributeMaxDynamicSharedMemorySize, SMEM_ALL);
    cudaFuncSetAttribute(sc_h,      cudaFuncAttributeMaxDynamicSharedMemorySize, SMEM_ALL);

    wconv_h<<<dim3(256, 4), 256>>>(Wq, Wk, Wv, Wo, Wt);
    ln_kernel<<<dim3(Ssz / 32, Bbat, 2), 256>>>(x_l, x_r, g1, b1, g2, b2,
                                                xln, xln + BSC);

    // Q, K, V projections — both sides per launch (576 CTAs each)
    gemm_h<0><<<dim3(288, 1, 2), 256, SMEM_ALL>>>(xln, 256, 0, BSC,
                                                  Wt + 0 * 65536, 256, 0, 0,
                                                  q, 0, BSC, 256, nullptr, nullptr);
    gemm_h<0><<<dim3(288, 1, 2), 256, SMEM_ALL>>>(xln, 256, 0, BSC,
                                                  Wt + 1 * 65536, 256, 0, 0,
                                                  k, 0, BSC, 256, nullptr, nullptr);
    gemm_h<1><<<dim3(288, 1, 2), 256, SMEM_ALL>>>(xln, 256, 0, BSC,
                                                  Wt + 2 * 65536, 256, 0, 0,
                                                  vt, 0, BSC, 256, nullptr, nullptr);

    // scores for both sides (648 CTAs), raw exp
    sc_h<<<dim3(18, 18, 2), 256, SMEM_ALL>>>(q, k, E);
    // batch-softmax normalize in place, both sides
    normalize_h<<<dim3((int)(SSl / 2048), 2), 256>>>(E);
    // PV for both sides (576 CTAs): O[b][s][c] = P[b] @ Vt[b]^T
    gemm_h<0><<<dim3(36, Bbat, 2), 256, SMEM_ALL>>>(E, Ssz, SSl, ESIDE,
                                                    vt, Ssz, (long)Csz * Ssz, (long)BSC,
                                                    O, (long)Ssz * Csz, (long)BSC,
                                                    Ssz, nullptr, nullptr);
    // output projection + residual + transpose back, both sides (576 CTAs)
    gemm_h<2><<<dim3(288, 1, 2), 256, SMEM_ALL>>>(O, 256, 0, BSC,
                                                  Wt + 3 * 65536, 256, 0, 0,
                                                  out, 0, BSC, 256, x_l, x_r);
}